// round 10
// baseline (speedup 1.0000x reference)
#include <cuda_runtime.h>
#include <cuda_fp16.h>
#include <cstddef>

#define NNODES 100000
#define NEDGES 1600000
#define NFEAT  7
#define HID    128
#define NGRAPH 8
#define NCLASS 5

// ---------------------------------------------------------------------------
// Device-global scratch (allocation-free contract)
// ---------------------------------------------------------------------------
__device__ int    g_rowptr[NNODES + 1];
__device__ int    g_cur[NNODES];
__device__ int2   g_epack[NEDGES];        // CSR slot: {src, attr bits}
__device__ float  g_agg7[NNODES * NFEAT];
__device__ float  g_agg[NNODES * HID];
__device__ float  g_ha[NNODES * HID];
__device__ float  g_hb[NNODES * HID];
__device__ __half g_h16[NNODES * HID];    // fp16 copy of current h (neighbor reads)
__device__ float  g_pool[NGRAPH * HID];
__device__ float  g_cnt[NGRAPH];

// ---------------------------------------------------------------------------
// CSR build: histogram -> scan -> fill
// ---------------------------------------------------------------------------
__global__ void hist_kernel(const int* __restrict__ ei) {
    int e = blockIdx.x * blockDim.x + threadIdx.x;
    if (e < NEDGES) atomicAdd(&g_cur[ei[NEDGES + e]], 1);
}

__global__ void scan_kernel() {
    __shared__ int warp_sums[32];
    __shared__ int s_carry;
    int tid = threadIdx.x;
    int lane = tid & 31, wid = tid >> 5;
    if (tid == 0) s_carry = 0;
    __syncthreads();
    for (int base = 0; base < NNODES; base += 1024) {
        int i = base + tid;
        int v = (i < NNODES) ? g_cur[i] : 0;
        int incl = v;
#pragma unroll
        for (int o = 1; o < 32; o <<= 1) {
            int t = __shfl_up_sync(0xffffffffu, incl, o);
            if (lane >= o) incl += t;
        }
        if (lane == 31) warp_sums[wid] = incl;
        __syncthreads();
        if (wid == 0) {
            int ws = warp_sums[lane];
            int wincl = ws;
#pragma unroll
            for (int o = 1; o < 32; o <<= 1) {
                int t = __shfl_up_sync(0xffffffffu, wincl, o);
                if (lane >= o) wincl += t;
            }
            warp_sums[lane] = wincl - ws;
        }
        __syncthreads();
        int excl = incl - v + warp_sums[wid] + s_carry;
        if (i < NNODES) { g_rowptr[i] = excl; g_cur[i] = excl; }
        __syncthreads();
        if (tid == 1023) s_carry = excl + v;
        __syncthreads();
    }
    if (tid == 0) g_rowptr[NNODES] = NEDGES;
}

__global__ void fill_kernel(const int* __restrict__ ei, const float* __restrict__ ea) {
    int e = blockIdx.x * blockDim.x + threadIdx.x;
    if (e >= NEDGES) return;
    int d = ei[NEDGES + e];
    int pos = atomicAdd(&g_cur[d], 1);
    g_epack[pos] = make_int2(ei[e], __float_as_int(ea[e]));
}

// ---------------------------------------------------------------------------
// Layer 1 gather: thread per node, 7 features, 4-edge unroll
// ---------------------------------------------------------------------------
__global__ void gather7(const float* __restrict__ x, const float* __restrict__ We,
                        const float* __restrict__ be) {
    int n = blockIdx.x * blockDim.x + threadIdx.x;
    if (n >= NNODES) return;
    float w[NFEAT], bb[NFEAT], acc[NFEAT];
#pragma unroll
    for (int f = 0; f < NFEAT; f++) { w[f] = __ldg(&We[f]); bb[f] = __ldg(&be[f]); }
#pragma unroll
    for (int f = 0; f < NFEAT; f++) acc[f] = x[n * NFEAT + f];
    int beg = g_rowptr[n], end = g_rowptr[n + 1];
    int e = beg;
    for (; e + 3 < end; e += 4) {
        int2 p0 = __ldg(&g_epack[e]),     p1 = __ldg(&g_epack[e + 1]);
        int2 p2 = __ldg(&g_epack[e + 2]), p3 = __ldg(&g_epack[e + 3]);
        float a0 = __int_as_float(p0.y), a1 = __int_as_float(p1.y);
        float a2 = __int_as_float(p2.y), a3 = __int_as_float(p3.y);
        float v0[NFEAT], v1[NFEAT], v2[NFEAT], v3[NFEAT];
#pragma unroll
        for (int f = 0; f < NFEAT; f++) v0[f] = __ldg(&x[p0.x * NFEAT + f]);
#pragma unroll
        for (int f = 0; f < NFEAT; f++) v1[f] = __ldg(&x[p1.x * NFEAT + f]);
#pragma unroll
        for (int f = 0; f < NFEAT; f++) v2[f] = __ldg(&x[p2.x * NFEAT + f]);
#pragma unroll
        for (int f = 0; f < NFEAT; f++) v3[f] = __ldg(&x[p3.x * NFEAT + f]);
#pragma unroll
        for (int f = 0; f < NFEAT; f++) {
            acc[f] += fmaxf(v0[f] + fmaf(a0, w[f], bb[f]), 0.f)
                    + fmaxf(v1[f] + fmaf(a1, w[f], bb[f]), 0.f)
                    + fmaxf(v2[f] + fmaf(a2, w[f], bb[f]), 0.f)
                    + fmaxf(v3[f] + fmaf(a3, w[f], bb[f]), 0.f);
        }
    }
    for (; e < end; e++) {
        int2 p = __ldg(&g_epack[e]);
        float a = __int_as_float(p.y);
#pragma unroll
        for (int f = 0; f < NFEAT; f++)
            acc[f] += fmaxf(__ldg(&x[p.x * NFEAT + f]) + fmaf(a, w[f], bb[f]), 0.f);
    }
#pragma unroll
    for (int f = 0; f < NFEAT; f++) g_agg7[n * NFEAT + f] = acc[f];
}

// ---------------------------------------------------------------------------
// Layer 1 dense: writes fp32 h1 AND fp16 copy
// ---------------------------------------------------------------------------
__global__ void dense7(const float* __restrict__ W, const float* __restrict__ b) {
    __shared__ float sW[NFEAT * HID];
    __shared__ float sb[HID];
    __shared__ float sAgg[256 * NFEAT];
    int t = threadIdx.x;  // 0..127
    for (int i = t; i < NFEAT * HID; i += 128) sW[i] = W[i];
    sb[t] = b[t];

    int n0 = blockIdx.x * 256;
    int cnt = NNODES - n0; if (cnt > 256) cnt = 256;
    for (int i = t; i < cnt * NFEAT; i += 128) sAgg[i] = g_agg7[n0 * NFEAT + i];
    __syncthreads();

    for (int r = 0; r < cnt; r++) {
        float acc = sb[t];
#pragma unroll
        for (int k = 0; k < NFEAT; k++)
            acc = fmaf(sAgg[r * NFEAT + k], sW[k * HID + t], acc);
        float o = fmaxf(acc, 0.f);
        size_t idx = (size_t)(n0 + r) * HID + t;
        g_ha[idx]  = o;
        g_h16[idx] = __float2half_rn(o);
    }
}

// ---------------------------------------------------------------------------
// 128-feat gather: warp per node, fp16 rows, 16 edges per latency round
// (clamp-masked loads: one epack round + 16 independent row loads in flight)
// ---------------------------------------------------------------------------
__device__ __forceinline__ void acc_edge(float4& acc, uint2 v, float a,
                                         const float4& w, const float4& bb) {
    __half2 h0 = *reinterpret_cast<__half2*>(&v.x);
    __half2 h1 = *reinterpret_cast<__half2*>(&v.y);
    float2 f0 = __half22float2(h0);
    float2 f1 = __half22float2(h1);
    acc.x += fmaxf(f0.x + fmaf(a, w.x, bb.x), 0.f);
    acc.y += fmaxf(f0.y + fmaf(a, w.y, bb.y), 0.f);
    acc.z += fmaxf(f1.x + fmaf(a, w.z, bb.z), 0.f);
    acc.w += fmaxf(f1.y + fmaf(a, w.w, bb.w), 0.f);
}

__global__ void __launch_bounds__(256)
gather128(const float* __restrict__ h32, const float* __restrict__ We,
          const float* __restrict__ be, float* __restrict__ aggout) {
    int warp = (blockIdx.x * blockDim.x + threadIdx.x) >> 5;
    int lane = threadIdx.x & 31;
    if (warp >= NNODES) return;
    float4 w  = __ldg(&((const float4*)We)[lane]);
    float4 bb = __ldg(&((const float4*)be)[lane]);
    int beg = __ldg(&g_rowptr[warp]);
    int end = __ldg(&g_rowptr[warp + 1]);
    const uint2* h16 = (const uint2*)g_h16;
    float4 acc = ((const float4*)h32)[(size_t)warp * 32 + lane];

    for (int base = beg; base < end; base += 16) {
        int m = end - base;                 // >= 1
        int   s[16];
        float a[16];
#pragma unroll
        for (int i = 0; i < 16; i++) {
            int idx = base + (i < m ? i : m - 1);   // clamp: always valid
            int2 p = __ldg(&g_epack[idx]);
            s[i] = p.x;
            a[i] = __int_as_float(p.y);
        }
        uint2 v[16];
#pragma unroll
        for (int i = 0; i < 16; i++)
            v[i] = __ldg(&h16[(size_t)s[i] * 32 + lane]);
#pragma unroll
        for (int i = 0; i < 16; i++)
            if (i < m) acc_edge(acc, v[i], a[i], w, bb);
    }
    ((float4*)aggout)[(size_t)warp * 32 + lane] = acc;
}

// ---------------------------------------------------------------------------
// Dense 128x128 FFMA (known-good): out[n,:] = relu( A[n,:] @ W + b )
// Tile: 64 nodes x 128 outs, 256 threads, 8x4 register block, W+A in smem
// ---------------------------------------------------------------------------
__global__ void dense128(const float* __restrict__ A, const float* __restrict__ W,
                         const float* __restrict__ b, float* __restrict__ out,
                         int write16) {
    extern __shared__ float sm[];
    float* sW = sm;              // 64KB
    float* sA = sm + HID * HID;  // 32KB
    int t = threadIdx.x;         // 0..255
    int m0 = blockIdx.x * 64;

    {
        float4* dW = (float4*)sW;
        const float4* gW = (const float4*)W;
        for (int i = t; i < HID * HID / 4; i += 256) dW[i] = gW[i];
    }
    {
        float4* dA = (float4*)sA;
        for (int i = t; i < 64 * 32; i += 256) {
            int r = i >> 5, c = i & 31;
            int n = m0 + r;
            float4 v = make_float4(0.f, 0.f, 0.f, 0.f);
            if (n < NNODES) v = ((const float4*)A)[(size_t)n * 32 + c];
            dA[i] = v;
        }
    }
    __syncthreads();

    int tn = t & 31;
    int tm = t >> 5;
    float acc[8][4];
#pragma unroll
    for (int i = 0; i < 8; i++)
#pragma unroll
        for (int j = 0; j < 4; j++) acc[i][j] = 0.f;

#pragma unroll 8
    for (int k4 = 0; k4 < 32; k4++) {
        float4 a4[8];
#pragma unroll
        for (int i = 0; i < 8; i++)
            a4[i] = ((float4*)(sA + (tm * 8 + i) * HID))[k4];
#pragma unroll
        for (int kk = 0; kk < 4; kk++) {
            float4 w4 = ((float4*)(sW + (k4 * 4 + kk) * HID))[tn];
#pragma unroll
            for (int i = 0; i < 8; i++) {
                float av = (kk == 0) ? a4[i].x : (kk == 1) ? a4[i].y
                         : (kk == 2) ? a4[i].z : a4[i].w;
                acc[i][0] = fmaf(av, w4.x, acc[i][0]);
                acc[i][1] = fmaf(av, w4.y, acc[i][1]);
                acc[i][2] = fmaf(av, w4.z, acc[i][2]);
                acc[i][3] = fmaf(av, w4.w, acc[i][3]);
            }
        }
    }

    float4 bb = __ldg(&((const float4*)b)[tn]);
#pragma unroll
    for (int i = 0; i < 8; i++) {
        int n = m0 + tm * 8 + i;
        if (n < NNODES) {
            float4 o;
            o.x = fmaxf(acc[i][0] + bb.x, 0.f);
            o.y = fmaxf(acc[i][1] + bb.y, 0.f);
            o.z = fmaxf(acc[i][2] + bb.z, 0.f);
            o.w = fmaxf(acc[i][3] + bb.w, 0.f);
            ((float4*)out)[(size_t)n * 32 + tn] = o;
            if (write16) {
                uint2 hv;
                __half2 p0 = __floats2half2_rn(o.x, o.y);
                __half2 p1 = __floats2half2_rn(o.z, o.w);
                hv.x = *reinterpret_cast<unsigned*>(&p0);
                hv.y = *reinterpret_cast<unsigned*>(&p1);
                ((uint2*)g_h16)[(size_t)n * 32 + tn] = hv;
            }
        }
    }
}

// ---------------------------------------------------------------------------
// Pooling + head
// ---------------------------------------------------------------------------
__global__ void pool_init() {
    int t = blockIdx.x * blockDim.x + threadIdx.x;
    if (t < NGRAPH * HID) g_pool[t] = 0.f;
    if (t < NGRAPH) g_cnt[t] = 0.f;
}

__global__ void pool_kernel(const float* __restrict__ h, const int* __restrict__ batch) {
    int f = threadIdx.x;  // 0..127
    int n0 = blockIdx.x * 256;
    int n1 = n0 + 256; if (n1 > NNODES) n1 = NNODES;
    if (n0 >= NNODES) return;
    float acc = 0.f, c = 0.f;
    int curg = batch[n0];
    for (int n = n0; n < n1; n++) {
        int g = batch[n];
        if (g != curg) {
            atomicAdd(&g_pool[curg * HID + f], acc);
            if (f == 0) atomicAdd(&g_cnt[curg], c);
            acc = 0.f; c = 0.f; curg = g;
        }
        acc += h[(size_t)n * HID + f];
        c += 1.f;
    }
    atomicAdd(&g_pool[curg * HID + f], acc);
    if (f == 0) atomicAdd(&g_cnt[curg], c);
}

__global__ void final_kernel(const float* __restrict__ Wlin, const float* __restrict__ blin,
                             float* __restrict__ out) {
    int t = threadIdx.x;
    if (t >= NGRAPH * NCLASS) return;
    int g = t / NCLASS, c = t % NCLASS;
    float cnt = fmaxf(g_cnt[g], 1.f);
    float acc = blin[c];
#pragma unroll 8
    for (int f = 0; f < HID; f++)
        acc = fmaf(g_pool[g * HID + f] / cnt, Wlin[f * NCLASS + c], acc);
    out[t] = acc;
}

// ---------------------------------------------------------------------------
// Launch
// ---------------------------------------------------------------------------
extern "C" void kernel_launch(void* const* d_in, const int* in_sizes, int n_in,
                              void* d_out, int out_size) {
    const float* x     = (const float*)d_in[0];
    const int*   ei    = (const int*)d_in[1];
    const float* ea    = (const float*)d_in[2];
    const int*   batch = (const int*)d_in[3];
    const float* We1 = (const float*)d_in[4],  *be1 = (const float*)d_in[5];
    const float* W1  = (const float*)d_in[6],  *b1  = (const float*)d_in[7];
    const float* We2 = (const float*)d_in[8],  *be2 = (const float*)d_in[9];
    const float* W2  = (const float*)d_in[10], *b2  = (const float*)d_in[11];
    const float* We3 = (const float*)d_in[12], *be3 = (const float*)d_in[13];
    const float* W3  = (const float*)d_in[14], *b3  = (const float*)d_in[15];
    const float* Wlin = (const float*)d_in[16], *blin = (const float*)d_in[17];
    float* out = (float*)d_out;

    void *aggp, *hap, *hbp, *curp;
    cudaGetSymbolAddress(&aggp, g_agg);
    cudaGetSymbolAddress(&hap,  g_ha);
    cudaGetSymbolAddress(&hbp,  g_hb);
    cudaGetSymbolAddress(&curp, g_cur);
    float* agg = (float*)aggp;
    float* ha  = (float*)hap;
    float* hb  = (float*)hbp;

    cudaFuncSetAttribute(dense128, cudaFuncAttributeMaxDynamicSharedMemorySize, 98304);

    const int EBLK = (NEDGES + 255) / 256;
    const int G128_BLOCKS = (NNODES * 32 + 255) / 256;   // warp per node
    const int D128_BLOCKS = (NNODES + 63) / 64;

    // CSR build (reused by all 3 layers)
    cudaMemsetAsync(curp, 0, NNODES * sizeof(int), 0);
    hist_kernel<<<EBLK, 256>>>(ei);
    scan_kernel<<<1, 1024>>>();
    fill_kernel<<<EBLK, 256>>>(ei, ea);

    // Layer 1 (in = 7 feats)
    gather7<<<(NNODES + 255) / 256, 256>>>(x, We1, be1);
    dense7<<<(NNODES + 255) / 256, 128>>>(W1, b1);                // -> g_ha + g_h16

    // Layer 2
    gather128<<<G128_BLOCKS, 256>>>(ha, We2, be2, agg);           // reads g_h16 (h1)
    dense128<<<D128_BLOCKS, 256, 98304>>>(agg, W2, b2, hb, 1);    // -> g_hb + g_h16

    // Layer 3
    gather128<<<G128_BLOCKS, 256>>>(hb, We3, be3, agg);           // reads g_h16 (h2)
    dense128<<<D128_BLOCKS, 256, 98304>>>(agg, W3, b3, ha, 0);    // -> g_ha

    // Mean pool + linear head
    pool_init<<<8, 128>>>();
    pool_kernel<<<(NNODES + 255) / 256, 128>>>(ha, batch);
    final_kernel<<<1, 64>>>(Wlin, blin, out);
}